// round 2
// baseline (speedup 1.0000x reference)
#include <cuda_runtime.h>
#include <math.h>

#define NNODES 50000
#define MAXF   256
#define EPS    1e-5f

// ---------------- device scratch (no allocations allowed) ----------------
__device__ float g_bufA[(size_t)NNODES * MAXF];
__device__ float g_bufB[(size_t)NNODES * MAXF];
__device__ float g_dinv[NNODES];
__device__ int   g_deg[NNODES];

// ---------------- degree / dinv ----------------
__global__ void zero_deg_kernel(int* deg, int n) {
    int i = blockIdx.x * blockDim.x + threadIdx.x;
    if (i < n) deg[i] = 0;
}

__global__ void count_deg_kernel(const int* __restrict__ dst, int* deg, int E) {
    int i = blockIdx.x * blockDim.x + threadIdx.x;
    if (i < E) atomicAdd(&deg[dst[i]], 1);
}

__global__ void dinv_kernel(const int* __restrict__ deg, float* dinv, int n) {
    int i = blockIdx.x * blockDim.x + threadIdx.x;
    if (i < n) dinv[i] = rsqrtf((float)deg[i] + 1.0f);
}

// ---------------- tiled fp32 GEMM: C[M,Nc] = A[M,K] @ W[K,Nc] (+bias) ----------------
// BM=BN=64, BK=16, 256 threads, 4x4 microtile per thread. K must be mult of 16.
__global__ void gemm_kernel(const float* __restrict__ A, const float* __restrict__ W,
                            const float* __restrict__ bias, float* __restrict__ C,
                            int M, int K, int Nc, int addBias)
{
    __shared__ float As[16][64];
    __shared__ float Ws[16][64];

    const int tid = threadIdx.x;
    const int tx = tid & 15;       // 0..15 -> col group
    const int ty = tid >> 4;       // 0..15 -> row group
    const int rowBase = blockIdx.y * 64;
    const int colBase = blockIdx.x * 64;

    float acc[4][4];
    #pragma unroll
    for (int i = 0; i < 4; i++)
        #pragma unroll
        for (int j = 0; j < 4; j++) acc[i][j] = 0.0f;

    for (int k0 = 0; k0 < K; k0 += 16) {
        // load A tile (64 rows x 16 cols), store transposed: As[c][r]
        #pragma unroll
        for (int t = 0; t < 4; t++) {
            int lin = t * 256 + tid;        // 0..1023
            int r = lin >> 4;               // 0..63
            int c = lin & 15;               // 0..15
            float v = 0.0f;
            int gr = rowBase + r;
            if (gr < M) v = A[(size_t)gr * K + k0 + c];
            As[c][r] = v;
        }
        // load W tile (16 rows x 64 cols)
        #pragma unroll
        for (int t = 0; t < 4; t++) {
            int lin = t * 256 + tid;
            int r = lin >> 6;               // 0..15
            int c = lin & 63;               // 0..63
            float v = 0.0f;
            int gc = colBase + c;
            if (gc < Nc) v = W[(size_t)(k0 + r) * Nc + gc];
            Ws[r][c] = v;
        }
        __syncthreads();

        #pragma unroll
        for (int k = 0; k < 16; k++) {
            float a[4], b[4];
            #pragma unroll
            for (int i = 0; i < 4; i++) a[i] = As[k][ty * 4 + i];
            #pragma unroll
            for (int j = 0; j < 4; j++) b[j] = Ws[k][tx * 4 + j];
            #pragma unroll
            for (int i = 0; i < 4; i++)
                #pragma unroll
                for (int j = 0; j < 4; j++) acc[i][j] += a[i] * b[j];
        }
        __syncthreads();
    }

    #pragma unroll
    for (int i = 0; i < 4; i++) {
        int gr = rowBase + ty * 4 + i;
        if (gr >= M) continue;
        #pragma unroll
        for (int j = 0; j < 4; j++) {
            int gc = colBase + tx * 4 + j;
            if (gc >= Nc) continue;
            float v = acc[i][j];
            if (addBias) v += bias[gc];
            C[(size_t)gr * Nc + gc] = v;
        }
    }
}

// ---------------- agg init: agg[i][f] = h[i][f]*dinv[i]^2 + b[f] ----------------
__global__ void selfloop_init_kernel(const float* __restrict__ h, const float* __restrict__ dinv,
                                     const float* __restrict__ bias, float* __restrict__ agg,
                                     int n, int F)
{
    int idx = blockIdx.x * blockDim.x + threadIdx.x;
    int total = n * F;
    if (idx >= total) return;
    int row = idx / F;
    int f = idx - row * F;
    float d = dinv[row];
    agg[idx] = h[idx] * d * d + bias[f];
}

// ---------------- edge scatter: one warp per edge, atomicAdd to agg[dst] ----------------
__global__ void scatter_kernel(const float* __restrict__ h, const float* __restrict__ dinv,
                               const int* __restrict__ src, const int* __restrict__ dst,
                               float* __restrict__ agg, int E, int F)
{
    int warp = (blockIdx.x * blockDim.x + threadIdx.x) >> 5;
    int lane = threadIdx.x & 31;
    if (warp >= E) return;
    int s = src[warp];
    int d = dst[warp];
    float coef = dinv[s] * dinv[d];
    const float4* hs = (const float4*)(h + (size_t)s * F);
    float* ad = agg + (size_t)d * F;
    int nvec = F >> 2;
    for (int v = lane; v < nvec; v += 32) {
        float4 val = hs[v];
        atomicAdd(ad + 4 * v + 0, val.x * coef);
        atomicAdd(ad + 4 * v + 1, val.y * coef);
        atomicAdd(ad + 4 * v + 2, val.z * coef);
        atomicAdd(ad + 4 * v + 3, val.w * coef);
    }
}

// ---------------- fused LayerNorm + ELU, one warp per row, in place ----------------
__global__ void ln_elu_kernel(float* __restrict__ h, const float* __restrict__ g,
                              const float* __restrict__ b, int n, int F)
{
    int row = (blockIdx.x * blockDim.x + threadIdx.x) >> 5;
    int lane = threadIdx.x & 31;
    if (row >= n) return;
    float* hr = h + (size_t)row * F;
    int per = F >> 5;                // F/32, <= 8
    float vals[8];
    float sum = 0.0f;
    for (int i = 0; i < per; i++) {
        vals[i] = hr[lane + 32 * i];
        sum += vals[i];
    }
    #pragma unroll
    for (int o = 16; o > 0; o >>= 1) sum += __shfl_xor_sync(0xFFFFFFFFu, sum, o);
    float mu = sum / (float)F;
    float vsum = 0.0f;
    for (int i = 0; i < per; i++) {
        float dv = vals[i] - mu;
        vsum += dv * dv;
    }
    #pragma unroll
    for (int o = 16; o > 0; o >>= 1) vsum += __shfl_xor_sync(0xFFFFFFFFu, vsum, o);
    float rstd = rsqrtf(vsum / (float)F + EPS);
    for (int i = 0; i < per; i++) {
        int f = lane + 32 * i;
        float y = (vals[i] - mu) * rstd * g[f] + b[f];
        hr[f] = (y > 0.0f) ? y : expm1f(y);
    }
}

// ---------------- host ----------------
extern "C" void kernel_launch(void* const* d_in, const int* in_sizes, int n_in,
                              void* d_out, int out_size)
{
    const float* x    = (const float*)d_in[0];
    const int* eidx   = (const int*)d_in[1];
    const float* W1   = (const float*)d_in[2];
    const float* b1   = (const float*)d_in[3];
    const float* g1   = (const float*)d_in[4];
    const float* be1  = (const float*)d_in[5];
    const float* W2   = (const float*)d_in[6];
    const float* b2   = (const float*)d_in[7];
    const float* g2   = (const float*)d_in[8];
    const float* be2  = (const float*)d_in[9];
    const float* W3   = (const float*)d_in[10];
    const float* b3   = (const float*)d_in[11];
    const float* g3   = (const float*)d_in[12];
    const float* be3  = (const float*)d_in[13];
    const float* Wl1  = (const float*)d_in[14];
    const float* bl1  = (const float*)d_in[15];
    const float* g4   = (const float*)d_in[16];
    const float* be4  = (const float*)d_in[17];
    const float* Wl2  = (const float*)d_in[18];
    const float* bl2  = (const float*)d_in[19];
    float* out = (float*)d_out;

    const int N = in_sizes[0] / 128;      // 50000
    const int E = in_sizes[1] / 2;        // 800000
    const int IN = 128, H = 128, H2 = 256, HL = 64, OUT = 500;

    const int* src = eidx;
    const int* dst = eidx + E;

    float *bufA, *bufB, *dinv;
    int* deg;
    cudaGetSymbolAddress((void**)&bufA, g_bufA);
    cudaGetSymbolAddress((void**)&bufB, g_bufB);
    cudaGetSymbolAddress((void**)&dinv, g_dinv);
    cudaGetSymbolAddress((void**)&deg, g_deg);

    // degree / dinv
    zero_deg_kernel<<<(N + 255) / 256, 256>>>(deg, N);
    count_deg_kernel<<<(E + 255) / 256, 256>>>(dst, deg, E);
    dinv_kernel<<<(N + 255) / 256, 256>>>(deg, dinv, N);

    dim3 gThr(256);
    auto gemmGrid = [](int M, int Nc) { return dim3((Nc + 63) / 64, (M + 63) / 64); };
    int scatterBlocks = (E + 7) / 8;             // 8 warps per 256-thr block
    int lnBlocks = (N + 7) / 8;

    // --- GCN layer 1: 128 -> 128 ---
    gemm_kernel<<<gemmGrid(N, H), gThr>>>(x, W1, nullptr, bufA, N, IN, H, 0);
    selfloop_init_kernel<<<(N * H + 255) / 256, 256>>>(bufA, dinv, b1, bufB, N, H);
    scatter_kernel<<<scatterBlocks, 256>>>(bufA, dinv, src, dst, bufB, E, H);
    ln_elu_kernel<<<lnBlocks, 256>>>(bufB, g1, be1, N, H);

    // --- GCN layer 2: 128 -> 256 ---
    gemm_kernel<<<gemmGrid(N, H2), gThr>>>(bufB, W2, nullptr, bufA, N, H, H2, 0);
    selfloop_init_kernel<<<(N * H2 + 255) / 256, 256>>>(bufA, dinv, b2, bufB, N, H2);
    scatter_kernel<<<scatterBlocks, 256>>>(bufA, dinv, src, dst, bufB, E, H2);
    ln_elu_kernel<<<lnBlocks, 256>>>(bufB, g2, be2, N, H2);

    // --- GCN layer 3: 256 -> 128 ---
    gemm_kernel<<<gemmGrid(N, H), gThr>>>(bufB, W3, nullptr, bufA, N, H2, H, 0);
    selfloop_init_kernel<<<(N * H + 255) / 256, 256>>>(bufA, dinv, b3, bufB, N, H);
    scatter_kernel<<<scatterBlocks, 256>>>(bufA, dinv, src, dst, bufB, E, H);
    ln_elu_kernel<<<lnBlocks, 256>>>(bufB, g3, be3, N, H);

    // --- Linear 128 -> 64, LN, ELU ---
    gemm_kernel<<<gemmGrid(N, HL), gThr>>>(bufB, Wl1, bl1, bufA, N, H, HL, 1);
    ln_elu_kernel<<<lnBlocks, 256>>>(bufA, g4, be4, N, HL);

    // --- Linear 64 -> 500 (output) ---
    gemm_kernel<<<gemmGrid(N, OUT), gThr>>>(bufA, Wl2, bl2, out, N, HL, OUT, 1);

    (void)n_in; (void)out_size;
}

// round 5
// speedup vs baseline: 2.5368x; 2.5368x over previous
#include <cuda_runtime.h>
#include <math.h>

#define NNODES 50000
#define NEDGES 800000
#define MAXF   256
#define EPS    1e-5f

// ---------------- device scratch (no allocations allowed) ----------------
__device__ float g_bufA[(size_t)NNODES * MAXF];
__device__ float g_bufB[(size_t)NNODES * MAXF];
__device__ float g_dinv[NNODES];
__device__ int   g_deg[NNODES];
__device__ int   g_rowptr[NNODES + 1];
__device__ int   g_cursor[NNODES];
__device__ int   g_csr_src[NEDGES];
__device__ float g_csr_coef[NEDGES];

// ---------------- degree / dinv ----------------
__global__ void zero_deg_kernel(int* deg, int n) {
    int i = blockIdx.x * blockDim.x + threadIdx.x;
    if (i < n) deg[i] = 0;
}

__global__ void count_deg_kernel(const int* __restrict__ dst, int* deg, int E) {
    int i = blockIdx.x * blockDim.x + threadIdx.x;
    if (i < E) atomicAdd(&deg[dst[i]], 1);
}

__global__ void dinv_kernel(const int* __restrict__ deg, float* dinv, int n) {
    int i = blockIdx.x * blockDim.x + threadIdx.x;
    if (i < n) dinv[i] = rsqrtf((float)deg[i] + 1.0f);
}

// ---------------- single-block scan: rowptr (inclusive shifted) + cursor (exclusive) ----------------
__global__ void scan_kernel(const int* __restrict__ deg, int* rowptr, int* cursor, int n)
{
    __shared__ int warpsums[32];
    __shared__ int carry_sh;
    if (threadIdx.x == 0) { carry_sh = 0; rowptr[0] = 0; }
    __syncthreads();

    int lane = threadIdx.x & 31;
    int wid = threadIdx.x >> 5;

    for (int base = 0; base < n; base += 1024) {
        int i = base + (int)threadIdx.x;
        int v = (i < n) ? deg[i] : 0;
        int x = v;
        #pragma unroll
        for (int o = 1; o < 32; o <<= 1) {
            int t = __shfl_up_sync(0xFFFFFFFFu, x, o);
            if (lane >= o) x += t;
        }
        if (lane == 31) warpsums[wid] = x;
        __syncthreads();
        if (wid == 0) {
            int s = warpsums[lane];
            #pragma unroll
            for (int o = 1; o < 32; o <<= 1) {
                int t = __shfl_up_sync(0xFFFFFFFFu, s, o);
                if (lane >= o) s += t;
            }
            warpsums[lane] = s;
        }
        __syncthreads();
        int incl = x + (wid > 0 ? warpsums[wid - 1] : 0);
        int total = warpsums[31];
        int carry = carry_sh;
        if (i < n) {
            rowptr[i + 1] = carry + incl;
            cursor[i] = carry + incl - v;
        }
        __syncthreads();
        if (threadIdx.x == 0) carry_sh = carry + total;
        __syncthreads();
    }
}

// ---------------- CSR fill ----------------
__global__ void fill_csr_kernel(const int* __restrict__ src, const int* __restrict__ dst,
                                const float* __restrict__ dinv, int* cursor,
                                int* csr_src, float* csr_coef, int E)
{
    int e = blockIdx.x * blockDim.x + threadIdx.x;
    if (e >= E) return;
    int s = src[e];
    int d = dst[e];
    int p = atomicAdd(&cursor[d], 1);
    csr_src[p] = s;
    csr_coef[p] = dinv[s] * dinv[d];
}

// ---------------- fp32 GEMM: 128x128 tile, 8x8 microtile, BK=16 ----------------
__global__ __launch_bounds__(256, 2)
void gemm128_kernel(const float* __restrict__ A, const float* __restrict__ W,
                    const float* __restrict__ bias, float* __restrict__ C,
                    int M, int K, int Nc, int addBias)
{
    __shared__ float As[16][128];   // [k][row]
    __shared__ float Ws[16][128];   // [k][col]

    const int tid = threadIdx.x;
    const int tx = tid & 15;        // col group (8 cols)
    const int ty = tid >> 4;        // row group (8 rows)
    const int rowBase = blockIdx.y * 128;
    const int colBase = blockIdx.x * 128;

    float acc[8][8];
    #pragma unroll
    for (int i = 0; i < 8; i++)
        #pragma unroll
        for (int j = 0; j < 8; j++) acc[i][j] = 0.0f;

    for (int k0 = 0; k0 < K; k0 += 16) {
        // A tile: 128 rows x 16 k. 512 float4 total, 2 per thread.
        #pragma unroll
        for (int t = 0; t < 2; t++) {
            int lin = t * 256 + tid;        // 0..511
            int r = lin >> 2;               // 0..127
            int c4 = lin & 3;               // float4 index in k-dim
            float4 v = make_float4(0.f, 0.f, 0.f, 0.f);
            int gr = rowBase + r;
            if (gr < M)
                v = *(const float4*)(A + (size_t)gr * K + k0 + 4 * c4);
            As[4 * c4 + 0][r] = v.x;
            As[4 * c4 + 1][r] = v.y;
            As[4 * c4 + 2][r] = v.z;
            As[4 * c4 + 3][r] = v.w;
        }
        // W tile: 16 k x 128 cols. 512 float4, 2 per thread, coalesced.
        #pragma unroll
        for (int t = 0; t < 2; t++) {
            int lin = t * 256 + tid;        // 0..511
            int r = lin >> 5;               // 0..15
            int c4 = lin & 31;              // float4 in col-dim
            float4 v = make_float4(0.f, 0.f, 0.f, 0.f);
            int gc = colBase + 4 * c4;
            if (gc + 3 < Nc)                // Nc always multiple of 4
                v = *(const float4*)(W + (size_t)(k0 + r) * Nc + gc);
            *(float4*)&Ws[r][4 * c4] = v;
        }
        __syncthreads();

        #pragma unroll
        for (int k = 0; k < 16; k++) {
            float4 a0 = *(const float4*)&As[k][ty * 8];
            float4 a1 = *(const float4*)&As[k][ty * 8 + 4];
            float4 b0 = *(const float4*)&Ws[k][tx * 8];
            float4 b1 = *(const float4*)&Ws[k][tx * 8 + 4];
            float a[8] = {a0.x, a0.y, a0.z, a0.w, a1.x, a1.y, a1.z, a1.w};
            float b[8] = {b0.x, b0.y, b0.z, b0.w, b1.x, b1.y, b1.z, b1.w};
            #pragma unroll
            for (int i = 0; i < 8; i++)
                #pragma unroll
                for (int j = 0; j < 8; j++) acc[i][j] += a[i] * b[j];
        }
        __syncthreads();
    }

    #pragma unroll
    for (int i = 0; i < 8; i++) {
        int gr = rowBase + ty * 8 + i;
        if (gr >= M) continue;
        #pragma unroll
        for (int jj = 0; jj < 2; jj++) {
            int gc = colBase + tx * 8 + 4 * jj;
            if (gc + 3 >= Nc) continue;
            float4 v;
            v.x = acc[i][4 * jj + 0];
            v.y = acc[i][4 * jj + 1];
            v.z = acc[i][4 * jj + 2];
            v.w = acc[i][4 * jj + 3];
            if (addBias) {
                const float4 b4 = *(const float4*)(bias + gc);
                v.x += b4.x; v.y += b4.y; v.z += b4.z; v.w += b4.w;
            }
            *(float4*)(C + (size_t)gr * Nc + gc) = v;
        }
    }
}

// ---------------- fused CSR gather + self-loop + bias + LayerNorm + ELU ----------------
// One warp per destination node. F = 128 or 256 (V = F/128 float4 per lane).
template <int F>
__global__ void gather_ln_elu_kernel(const float* __restrict__ h,
                                     const float* __restrict__ dinv,
                                     const int* __restrict__ rowptr,
                                     const int* __restrict__ csr_src,
                                     const float* __restrict__ csr_coef,
                                     const float* __restrict__ bias,
                                     const float* __restrict__ g,
                                     const float* __restrict__ be,
                                     float* __restrict__ out, int n)
{
    constexpr int V = F / 128;
    int row = (blockIdx.x * blockDim.x + threadIdx.x) >> 5;
    int lane = threadIdx.x & 31;
    if (row >= n) return;

    float acc[4 * V];
    // self-loop: h[row] * dinv[row]^2
    {
        float dv = dinv[row];
        float d2 = dv * dv;
        const float4* hr = (const float4*)(h + (size_t)row * F);
        #pragma unroll
        for (int v = 0; v < V; v++) {
            float4 t = hr[lane + 32 * v];
            acc[4 * v + 0] = t.x * d2;
            acc[4 * v + 1] = t.y * d2;
            acc[4 * v + 2] = t.z * d2;
            acc[4 * v + 3] = t.w * d2;
        }
    }

    int e0 = rowptr[row];
    int e1 = rowptr[row + 1];
    #pragma unroll 2
    for (int e = e0; e < e1; e++) {
        int s = csr_src[e];
        float c = csr_coef[e];
        const float4* hs = (const float4*)(h + (size_t)s * F);
        #pragma unroll
        for (int v = 0; v < V; v++) {
            float4 t = hs[lane + 32 * v];
            acc[4 * v + 0] += t.x * c;
            acc[4 * v + 1] += t.y * c;
            acc[4 * v + 2] += t.z * c;
            acc[4 * v + 3] += t.w * c;
        }
    }

    // + bias
    #pragma unroll
    for (int v = 0; v < V; v++) {
        float4 b4 = ((const float4*)bias)[lane + 32 * v];
        acc[4 * v + 0] += b4.x;
        acc[4 * v + 1] += b4.y;
        acc[4 * v + 2] += b4.z;
        acc[4 * v + 3] += b4.w;
    }

    // LayerNorm across F (warp-wide)
    float sum = 0.0f;
    #pragma unroll
    for (int i = 0; i < 4 * V; i++) sum += acc[i];
    #pragma unroll
    for (int o = 16; o > 0; o >>= 1) sum += __shfl_xor_sync(0xFFFFFFFFu, sum, o);
    float mu = sum / (float)F;
    float vsum = 0.0f;
    #pragma unroll
    for (int i = 0; i < 4 * V; i++) {
        float d = acc[i] - mu;
        vsum += d * d;
    }
    #pragma unroll
    for (int o = 16; o > 0; o >>= 1) vsum += __shfl_xor_sync(0xFFFFFFFFu, vsum, o);
    float rstd = rsqrtf(vsum / (float)F + EPS);

    float4* outr = (float4*)(out + (size_t)row * F);
    #pragma unroll
    for (int v = 0; v < V; v++) {
        float4 g4 = ((const float4*)g)[lane + 32 * v];
        float4 b4 = ((const float4*)be)[lane + 32 * v];
        float4 r;
        float y;
        y = (acc[4 * v + 0] - mu) * rstd * g4.x + b4.x; r.x = (y > 0.f) ? y : expm1f(y);
        y = (acc[4 * v + 1] - mu) * rstd * g4.y + b4.y; r.y = (y > 0.f) ? y : expm1f(y);
        y = (acc[4 * v + 2] - mu) * rstd * g4.z + b4.z; r.z = (y > 0.f) ? y : expm1f(y);
        y = (acc[4 * v + 3] - mu) * rstd * g4.w + b4.w; r.w = (y > 0.f) ? y : expm1f(y);
        outr[lane + 32 * v] = r;
    }
}

// ---------------- standalone LayerNorm + ELU (for F=64 linear layer) ----------------
__global__ void ln_elu_kernel(float* __restrict__ h, const float* __restrict__ g,
                              const float* __restrict__ b, int n, int F)
{
    int row = (blockIdx.x * blockDim.x + threadIdx.x) >> 5;
    int lane = threadIdx.x & 31;
    if (row >= n) return;
    float* hr = h + (size_t)row * F;
    int per = F >> 5;
    float vals[8];
    float sum = 0.0f;
    for (int i = 0; i < per; i++) {
        vals[i] = hr[lane + 32 * i];
        sum += vals[i];
    }
    #pragma unroll
    for (int o = 16; o > 0; o >>= 1) sum += __shfl_xor_sync(0xFFFFFFFFu, sum, o);
    float mu = sum / (float)F;
    float vsum = 0.0f;
    for (int i = 0; i < per; i++) {
        float dv = vals[i] - mu;
        vsum += dv * dv;
    }
    #pragma unroll
    for (int o = 16; o > 0; o >>= 1) vsum += __shfl_xor_sync(0xFFFFFFFFu, vsum, o);
    float rstd = rsqrtf(vsum / (float)F + EPS);
    for (int i = 0; i < per; i++) {
        int f = lane + 32 * i;
        float y = (vals[i] - mu) * rstd * g[f] + b[f];
        hr[f] = (y > 0.0f) ? y : expm1f(y);
    }
}

// ---------------- host ----------------
extern "C" void kernel_launch(void* const* d_in, const int* in_sizes, int n_in,
                              void* d_out, int out_size)
{
    const float* x    = (const float*)d_in[0];
    const int* eidx   = (const int*)d_in[1];
    const float* W1   = (const float*)d_in[2];
    const float* b1   = (const float*)d_in[3];
    const float* g1   = (const float*)d_in[4];
    const float* be1  = (const float*)d_in[5];
    const float* W2   = (const float*)d_in[6];
    const float* b2   = (const float*)d_in[7];
    const float* g2   = (const float*)d_in[8];
    const float* be2  = (const float*)d_in[9];
    const float* W3   = (const float*)d_in[10];
    const float* b3   = (const float*)d_in[11];
    const float* g3   = (const float*)d_in[12];
    const float* be3  = (const float*)d_in[13];
    const float* Wl1  = (const float*)d_in[14];
    const float* bl1  = (const float*)d_in[15];
    const float* g4   = (const float*)d_in[16];
    const float* be4  = (const float*)d_in[17];
    const float* Wl2  = (const float*)d_in[18];
    const float* bl2  = (const float*)d_in[19];
    float* out = (float*)d_out;

    const int N = in_sizes[0] / 128;      // 50000
    const int E = in_sizes[1] / 2;        // 800000
    const int IN = 128, H = 128, H2 = 256, HL = 64, OUT = 500;

    const int* src = eidx;
    const int* dst = eidx + E;

    float *bufA, *bufB, *dinv, *csr_coef;
    int *deg, *rowptr, *cursor, *csr_src;
    cudaGetSymbolAddress((void**)&bufA, g_bufA);
    cudaGetSymbolAddress((void**)&bufB, g_bufB);
    cudaGetSymbolAddress((void**)&dinv, g_dinv);
    cudaGetSymbolAddress((void**)&deg, g_deg);
    cudaGetSymbolAddress((void**)&rowptr, g_rowptr);
    cudaGetSymbolAddress((void**)&cursor, g_cursor);
    cudaGetSymbolAddress((void**)&csr_src, g_csr_src);
    cudaGetSymbolAddress((void**)&csr_coef, g_csr_coef);

    // ---- build dinv + CSR (by dst) ----
    zero_deg_kernel<<<(N + 255) / 256, 256>>>(deg, N);
    count_deg_kernel<<<(E + 255) / 256, 256>>>(dst, deg, E);
    dinv_kernel<<<(N + 255) / 256, 256>>>(deg, dinv, N);
    scan_kernel<<<1, 1024>>>(deg, rowptr, cursor, N);
    fill_csr_kernel<<<(E + 255) / 256, 256>>>(src, dst, dinv, cursor, csr_src, csr_coef, E);

    auto gemmGrid = [](int M, int Nc) { return dim3((Nc + 127) / 128, (M + 127) / 128); };
    int warpBlocks = (N + 7) / 8;   // one warp per node, 256-thread blocks

    // --- GCN layer 1: 128 -> 128 ---
    gemm128_kernel<<<gemmGrid(N, H), 256>>>(x, W1, nullptr, bufA, N, IN, H, 0);
    gather_ln_elu_kernel<128><<<warpBlocks, 256>>>(bufA, dinv, rowptr, csr_src, csr_coef,
                                                   b1, g1, be1, bufB, N);

    // --- GCN layer 2: 128 -> 256 ---
    gemm128_kernel<<<gemmGrid(N, H2), 256>>>(bufB, W2, nullptr, bufA, N, H, H2, 0);
    gather_ln_elu_kernel<256><<<warpBlocks, 256>>>(bufA, dinv, rowptr, csr_src, csr_coef,
                                                   b2, g2, be2, bufB, N);

    // --- GCN layer 3: 256 -> 128 ---
    gemm128_kernel<<<gemmGrid(N, H), 256>>>(bufB, W3, nullptr, bufA, N, H2, H, 0);
    gather_ln_elu_kernel<128><<<warpBlocks, 256>>>(bufA, dinv, rowptr, csr_src, csr_coef,
                                                   b3, g3, be3, bufB, N);

    // --- Linear 128 -> 64, LN, ELU ---
    gemm128_kernel<<<gemmGrid(N, HL), 256>>>(bufB, Wl1, bl1, bufA, N, H, HL, 1);
    ln_elu_kernel<<<warpBlocks, 256>>>(bufA, g4, be4, N, HL);

    // --- Linear 64 -> 500 (output) ---
    gemm128_kernel<<<gemmGrid(N, OUT), 256>>>(bufA, Wl2, bl2, out, N, HL, OUT, 1);

    (void)n_in; (void)out_size;
}

// round 8
// speedup vs baseline: 3.7912x; 1.4945x over previous
#include <cuda_runtime.h>
#include <mma.h>
#include <math.h>

using namespace nvcuda;

#define NNODES 50000
#define NEDGES 800000
#define MAXF   256
#define EPS    1e-5f

// ---------------- device scratch (no allocations allowed) ----------------
__device__ float g_bufA[(size_t)NNODES * MAXF];
__device__ float g_bufB[(size_t)NNODES * MAXF];
__device__ float g_dinv[NNODES];
__device__ int   g_deg[NNODES];
__device__ int   g_rowptr[NNODES + 1];
__device__ int   g_cursor[NNODES];
__device__ int   g_csr_src[NEDGES];
__device__ float g_csr_coef[NEDGES];
__device__ int   g_incl[NNODES];
__device__ int   g_bsums[64];

// ---------------- degree / dinv ----------------
__global__ void zero_deg_kernel(int* deg, int n) {
    int i = blockIdx.x * blockDim.x + threadIdx.x;
    if (i < n) deg[i] = 0;
}

__global__ void count_deg_kernel(const int* __restrict__ dst, int* deg, int E) {
    int i = blockIdx.x * blockDim.x + threadIdx.x;
    if (i < E) atomicAdd(&deg[dst[i]], 1);
}

__global__ void dinv_kernel(const int* __restrict__ deg, float* dinv, int n) {
    int i = blockIdx.x * blockDim.x + threadIdx.x;
    if (i < n) dinv[i] = rsqrtf((float)deg[i] + 1.0f);
}

// ---------------- multi-block scan (3 stages) ----------------
__global__ void scan_partial_kernel(const int* __restrict__ deg, int* incl, int* bsums, int n)
{
    __shared__ int warpsums[32];
    int i = blockIdx.x * 1024 + threadIdx.x;
    int lane = threadIdx.x & 31;
    int wid = threadIdx.x >> 5;
    int v = (i < n) ? deg[i] : 0;
    int x = v;
    #pragma unroll
    for (int o = 1; o < 32; o <<= 1) {
        int t = __shfl_up_sync(0xFFFFFFFFu, x, o);
        if (lane >= o) x += t;
    }
    if (lane == 31) warpsums[wid] = x;
    __syncthreads();
    if (wid == 0) {
        int s = warpsums[lane];
        #pragma unroll
        for (int o = 1; o < 32; o <<= 1) {
            int t = __shfl_up_sync(0xFFFFFFFFu, s, o);
            if (lane >= o) s += t;
        }
        warpsums[lane] = s;
    }
    __syncthreads();
    int inclv = x + (wid > 0 ? warpsums[wid - 1] : 0);
    if (i < n) incl[i] = inclv;
    if (threadIdx.x == 1023) bsums[blockIdx.x] = inclv;
}

__global__ void scan_bsums_kernel(int* bsums, int nb)
{
    // tiny: serial exclusive scan by thread 0
    if (threadIdx.x == 0) {
        int run = 0;
        for (int b = 0; b < nb; b++) {
            int t = bsums[b];
            bsums[b] = run;
            run += t;
        }
    }
}

__global__ void scan_finalize_kernel(const int* __restrict__ deg, const int* __restrict__ incl,
                                     const int* __restrict__ bsums,
                                     int* rowptr, int* cursor, int n)
{
    int i = blockIdx.x * blockDim.x + threadIdx.x;
    if (i >= n) return;
    int val = bsums[i >> 10] + incl[i];
    rowptr[i + 1] = val;
    cursor[i] = val - deg[i];
    if (i == 0) rowptr[0] = 0;
}

// ---------------- CSR fill ----------------
__global__ void fill_csr_kernel(const int* __restrict__ src, const int* __restrict__ dst,
                                const float* __restrict__ dinv, int* cursor,
                                int* csr_src, float* csr_coef, int E)
{
    int e = blockIdx.x * blockDim.x + threadIdx.x;
    if (e >= E) return;
    int s = src[e];
    int d = dst[e];
    int p = atomicAdd(&cursor[d], 1);
    csr_src[p] = s;
    csr_coef[p] = dinv[s] * dinv[d];
}

// ---------------- TF32 wmma GEMM: C[M,Nc] = A[M,K] @ W[K,Nc] (+bias) ----------------
// 128x128 block tile, BK=16, 256 threads = 8 warps.
// Warp (wr = wid>>1, wc = wid&1) owns rows wr*32..+32 (2 frag rows) x cols wc*64..+64 (4 frag cols).
#define LDT 132   // smem leading dim (multiple of 4, conflict-shifted)

__global__ __launch_bounds__(256)
void gemm_tf32_kernel(const float* __restrict__ A, const float* __restrict__ W,
                      const float* __restrict__ bias, float* __restrict__ C,
                      int M, int K, int Nc, int addBias)
{
    __shared__ __align__(16) float As[16][LDT];   // [k][m]  (A col_major frags)
    __shared__ __align__(16) float Ws[16][LDT];   // [k][n]  (B row_major frags)
    __shared__ __align__(16) float scr[8][16 * 20];

    const int tid = threadIdx.x;
    const int wid = tid >> 5;
    const int lane = tid & 31;
    const int wr = wid >> 1;
    const int wc = wid & 1;
    const int rowBase = blockIdx.y * 128;
    const int colBase = blockIdx.x * 128;

    wmma::fragment<wmma::accumulator, 16, 16, 8, float> acc[2][4];
    #pragma unroll
    for (int i = 0; i < 2; i++)
        #pragma unroll
        for (int j = 0; j < 4; j++) wmma::fill_fragment(acc[i][j], 0.0f);

    for (int k0 = 0; k0 < K; k0 += 16) {
        // A tile: 128 rows x 16 k -> As[k][m], tf32-converted
        #pragma unroll
        for (int t = 0; t < 2; t++) {
            int lin = t * 256 + tid;        // 0..511
            int r = lin >> 2;               // 0..127
            int c4 = lin & 3;
            float4 v = make_float4(0.f, 0.f, 0.f, 0.f);
            int gr = rowBase + r;
            if (gr < M)
                v = *(const float4*)(A + (size_t)gr * K + k0 + 4 * c4);
            As[4 * c4 + 0][r] = wmma::__float_to_tf32(v.x);
            As[4 * c4 + 1][r] = wmma::__float_to_tf32(v.y);
            As[4 * c4 + 2][r] = wmma::__float_to_tf32(v.z);
            As[4 * c4 + 3][r] = wmma::__float_to_tf32(v.w);
        }
        // W tile: 16 k x 128 n -> Ws[k][n]
        #pragma unroll
        for (int t = 0; t < 2; t++) {
            int lin = t * 256 + tid;
            int r = lin >> 5;               // 0..15
            int c4 = lin & 31;
            float4 v = make_float4(0.f, 0.f, 0.f, 0.f);
            int gc = colBase + 4 * c4;
            if (gc + 3 < Nc)                // Nc multiple of 4
                v = *(const float4*)(W + (size_t)(k0 + r) * Nc + gc);
            v.x = wmma::__float_to_tf32(v.x);
            v.y = wmma::__float_to_tf32(v.y);
            v.z = wmma::__float_to_tf32(v.z);
            v.w = wmma::__float_to_tf32(v.w);
            *(float4*)&Ws[r][4 * c4] = v;
        }
        __syncthreads();

        #pragma unroll
        for (int ks = 0; ks < 16; ks += 8) {
            wmma::fragment<wmma::matrix_a, 16, 16, 8, wmma::precision::tf32, wmma::col_major> af[2];
            wmma::fragment<wmma::matrix_b, 16, 16, 8, wmma::precision::tf32, wmma::row_major> bf[4];
            #pragma unroll
            for (int i = 0; i < 2; i++)
                wmma::load_matrix_sync(af[i], &As[ks][wr * 32 + i * 16], LDT);
            #pragma unroll
            for (int j = 0; j < 4; j++)
                wmma::load_matrix_sync(bf[j], &Ws[ks][wc * 64 + j * 16], LDT);
            #pragma unroll
            for (int i = 0; i < 2; i++)
                #pragma unroll
                for (int j = 0; j < 4; j++)
                    wmma::mma_sync(acc[i][j], af[i], bf[j], acc[i][j]);
        }
        __syncthreads();
    }

    // bias via one extra MMA: a = ones column (k=0), b row 0 = bias
    if (addBias) {
        for (int idx = tid; idx < 8 * LDT; idx += 256) {
            int k = idx / LDT;
            int m = idx % LDT;
            As[k][m] = (k == 0 && m < 128) ? 1.0f : 0.0f;
            float bv = 0.0f;
            if (k == 0 && m < 128 && colBase + m < Nc) bv = bias[colBase + m];
            Ws[k][m] = wmma::__float_to_tf32(bv);
        }
        __syncthreads();
        wmma::fragment<wmma::matrix_a, 16, 16, 8, wmma::precision::tf32, wmma::col_major> af;
        wmma::fragment<wmma::matrix_b, 16, 16, 8, wmma::precision::tf32, wmma::row_major> bf[4];
        #pragma unroll
        for (int j = 0; j < 4; j++)
            wmma::load_matrix_sync(bf[j], &Ws[0][wc * 64 + j * 16], LDT);
        #pragma unroll
        for (int i = 0; i < 2; i++) {
            wmma::load_matrix_sync(af, &As[0][wr * 32 + i * 16], LDT);
            #pragma unroll
            for (int j = 0; j < 4; j++)
                wmma::mma_sync(acc[i][j], af, bf[j], acc[i][j]);
        }
    }

    // store
    #pragma unroll
    for (int i = 0; i < 2; i++) {
        #pragma unroll
        for (int j = 0; j < 4; j++) {
            int gr0 = rowBase + wr * 32 + i * 16;
            int gc0 = colBase + wc * 64 + j * 16;
            if (gr0 >= M || gc0 >= Nc) continue;
            if (gr0 + 15 < M && gc0 + 15 < Nc) {
                wmma::store_matrix_sync(C + (size_t)gr0 * Nc + gc0, acc[i][j], Nc, wmma::mem_row_major);
            } else {
                wmma::store_matrix_sync(scr[wid], acc[i][j], 20, wmma::mem_row_major);
                __syncwarp();
                for (int e = lane; e < 256; e += 32) {
                    int r = e >> 4, c = e & 15;
                    if (gr0 + r < M && gc0 + c < Nc)
                        C[(size_t)(gr0 + r) * Nc + gc0 + c] = scr[wid][r * 20 + c];
                }
                __syncwarp();
            }
        }
    }
}

// ---------------- fused CSR gather + self-loop + bias + LayerNorm + ELU ----------------
template <int F>
__global__ void gather_ln_elu_kernel(const float* __restrict__ h,
                                     const float* __restrict__ dinv,
                                     const int* __restrict__ rowptr,
                                     const int* __restrict__ csr_src,
                                     const float* __restrict__ csr_coef,
                                     const float* __restrict__ bias,
                                     const float* __restrict__ g,
                                     const float* __restrict__ be,
                                     float* __restrict__ out, int n)
{
    constexpr int V = F / 128;
    int row = (blockIdx.x * blockDim.x + threadIdx.x) >> 5;
    int lane = threadIdx.x & 31;
    if (row >= n) return;

    float acc[4 * V];
    {
        float dv = dinv[row];
        float d2 = dv * dv;
        const float4* hr = (const float4*)(h + (size_t)row * F);
        #pragma unroll
        for (int v = 0; v < V; v++) {
            float4 t = hr[lane + 32 * v];
            acc[4 * v + 0] = t.x * d2;
            acc[4 * v + 1] = t.y * d2;
            acc[4 * v + 2] = t.z * d2;
            acc[4 * v + 3] = t.w * d2;
        }
    }

    int e0 = rowptr[row];
    int e1 = rowptr[row + 1];
    #pragma unroll 2
    for (int e = e0; e < e1; e++) {
        int s = csr_src[e];
        float c = csr_coef[e];
        const float4* hs = (const float4*)(h + (size_t)s * F);
        #pragma unroll
        for (int v = 0; v < V; v++) {
            float4 t = hs[lane + 32 * v];
            acc[4 * v + 0] += t.x * c;
            acc[4 * v + 1] += t.y * c;
            acc[4 * v + 2] += t.z * c;
            acc[4 * v + 3] += t.w * c;
        }
    }

    #pragma unroll
    for (int v = 0; v < V; v++) {
        float4 b4 = ((const float4*)bias)[lane + 32 * v];
        acc[4 * v + 0] += b4.x;
        acc[4 * v + 1] += b4.y;
        acc[4 * v + 2] += b4.z;
        acc[4 * v + 3] += b4.w;
    }

    float sum = 0.0f;
    #pragma unroll
    for (int i = 0; i < 4 * V; i++) sum += acc[i];
    #pragma unroll
    for (int o = 16; o > 0; o >>= 1) sum += __shfl_xor_sync(0xFFFFFFFFu, sum, o);
    float mu = sum / (float)F;
    float vsum = 0.0f;
    #pragma unroll
    for (int i = 0; i < 4 * V; i++) {
        float d = acc[i] - mu;
        vsum += d * d;
    }
    #pragma unroll
    for (int o = 16; o > 0; o >>= 1) vsum += __shfl_xor_sync(0xFFFFFFFFu, vsum, o);
    float rstd = rsqrtf(vsum / (float)F + EPS);

    float4* outr = (float4*)(out + (size_t)row * F);
    #pragma unroll
    for (int v = 0; v < V; v++) {
        float4 g4 = ((const float4*)g)[lane + 32 * v];
        float4 b4 = ((const float4*)be)[lane + 32 * v];
        float4 r;
        float y;
        y = (acc[4 * v + 0] - mu) * rstd * g4.x + b4.x; r.x = (y > 0.f) ? y : expm1f(y);
        y = (acc[4 * v + 1] - mu) * rstd * g4.y + b4.y; r.y = (y > 0.f) ? y : expm1f(y);
        y = (acc[4 * v + 2] - mu) * rstd * g4.z + b4.z; r.z = (y > 0.f) ? y : expm1f(y);
        y = (acc[4 * v + 3] - mu) * rstd * g4.w + b4.w; r.w = (y > 0.f) ? y : expm1f(y);
        outr[lane + 32 * v] = r;
    }
}

// ---------------- standalone LayerNorm + ELU (F=64 linear layer) ----------------
__global__ void ln_elu_kernel(float* __restrict__ h, const float* __restrict__ g,
                              const float* __restrict__ b, int n, int F)
{
    int row = (blockIdx.x * blockDim.x + threadIdx.x) >> 5;
    int lane = threadIdx.x & 31;
    if (row >= n) return;
    float* hr = h + (size_t)row * F;
    int per = F >> 5;
    float vals[8];
    float sum = 0.0f;
    for (int i = 0; i < per; i++) {
        vals[i] = hr[lane + 32 * i];
        sum += vals[i];
    }
    #pragma unroll
    for (int o = 16; o > 0; o >>= 1) sum += __shfl_xor_sync(0xFFFFFFFFu, sum, o);
    float mu = sum / (float)F;
    float vsum = 0.0f;
    for (int i = 0; i < per; i++) {
        float dv = vals[i] - mu;
        vsum += dv * dv;
    }
    #pragma unroll
    for (int o = 16; o > 0; o >>= 1) vsum += __shfl_xor_sync(0xFFFFFFFFu, vsum, o);
    float rstd = rsqrtf(vsum / (float)F + EPS);
    for (int i = 0; i < per; i++) {
        int f = lane + 32 * i;
        float y = (vals[i] - mu) * rstd * g[f] + b[f];
        hr[f] = (y > 0.0f) ? y : expm1f(y);
    }
}

// ---------------- host ----------------
extern "C" void kernel_launch(void* const* d_in, const int* in_sizes, int n_in,
                              void* d_out, int out_size)
{
    const float* x    = (const float*)d_in[0];
    const int* eidx   = (const int*)d_in[1];
    const float* W1   = (const float*)d_in[2];
    const float* b1   = (const float*)d_in[3];
    const float* g1   = (const float*)d_in[4];
    const float* be1  = (const float*)d_in[5];
    const float* W2   = (const float*)d_in[6];
    const float* b2   = (const float*)d_in[7];
    const float* g2   = (const float*)d_in[8];
    const float* be2  = (const float*)d_in[9];
    const float* W3   = (const float*)d_in[10];
    const float* b3   = (const float*)d_in[11];
    const float* g3   = (const float*)d_in[12];
    const float* be3  = (const float*)d_in[13];
    const float* Wl1  = (const float*)d_in[14];
    const float* bl1  = (const float*)d_in[15];
    const float* g4   = (const float*)d_in[16];
    const float* be4  = (const float*)d_in[17];
    const float* Wl2  = (const float*)d_in[18];
    const float* bl2  = (const float*)d_in[19];
    float* out = (float*)d_out;

    const int N = in_sizes[0] / 128;      // 50000
    const int E = in_sizes[1] / 2;        // 800000
    const int IN = 128, H = 128, H2 = 256, HL = 64, OUT = 500;

    const int* src = eidx;
    const int* dst = eidx + E;

    float *bufA, *bufB, *dinv, *csr_coef;
    int *deg, *rowptr, *cursor, *csr_src, *incl, *bsums;
    cudaGetSymbolAddress((void**)&bufA, g_bufA);
    cudaGetSymbolAddress((void**)&bufB, g_bufB);
    cudaGetSymbolAddress((void**)&dinv, g_dinv);
    cudaGetSymbolAddress((void**)&deg, g_deg);
    cudaGetSymbolAddress((void**)&rowptr, g_rowptr);
    cudaGetSymbolAddress((void**)&cursor, g_cursor);
    cudaGetSymbolAddress((void**)&csr_src, g_csr_src);
    cudaGetSymbolAddress((void**)&csr_coef, g_csr_coef);
    cudaGetSymbolAddress((void**)&incl, g_incl);
    cudaGetSymbolAddress((void**)&bsums, g_bsums);

    // ---- build dinv + CSR (by dst) ----
    zero_deg_kernel<<<(N + 255) / 256, 256>>>(deg, N);
    count_deg_kernel<<<(E + 255) / 256, 256>>>(dst, deg, E);
    dinv_kernel<<<(N + 255) / 256, 256>>>(deg, dinv, N);
    int nb = (N + 1023) / 1024;
    scan_partial_kernel<<<nb, 1024>>>(deg, incl, bsums, N);
    scan_bsums_kernel<<<1, 32>>>(bsums, nb);
    scan_finalize_kernel<<<(N + 255) / 256, 256>>>(deg, incl, bsums, rowptr, cursor, N);
    fill_csr_kernel<<<(E + 255) / 256, 256>>>(src, dst, dinv, cursor, csr_src, csr_coef, E);

    auto gemmGrid = [](int M, int Nc) { return dim3((Nc + 127) / 128, (M + 127) / 128); };
    int warpBlocks = (N + 7) / 8;

    // --- GCN layer 1: 128 -> 128 ---
    gemm_tf32_kernel<<<gemmGrid(N, H), 256>>>(x, W1, nullptr, bufA, N, IN, H, 0);
    gather_ln_elu_kernel<128><<<warpBlocks, 256>>>(bufA, dinv, rowptr, csr_src, csr_coef,
                                                   b1, g1, be1, bufB, N);

    // --- GCN layer 2: 128 -> 256 ---
    gemm_tf32_kernel<<<gemmGrid(N, H2), 256>>>(bufB, W2, nullptr, bufA, N, H, H2, 0);
    gather_ln_elu_kernel<256><<<warpBlocks, 256>>>(bufA, dinv, rowptr, csr_src, csr_coef,
                                                   b2, g2, be2, bufB, N);

    // --- GCN layer 3: 256 -> 128 ---
    gemm_tf32_kernel<<<gemmGrid(N, H), 256>>>(bufB, W3, nullptr, bufA, N, H2, H, 0);
    gather_ln_elu_kernel<128><<<warpBlocks, 256>>>(bufA, dinv, rowptr, csr_src, csr_coef,
                                                   b3, g3, be3, bufB, N);

    // --- Linear 128 -> 64, LN, ELU ---
    gemm_tf32_kernel<<<gemmGrid(N, HL), 256>>>(bufB, Wl1, bl1, bufA, N, H, HL, 1);
    ln_elu_kernel<<<warpBlocks, 256>>>(bufA, g4, be4, N, HL);

    // --- Linear 64 -> 500 (output) ---
    gemm_tf32_kernel<<<gemmGrid(N, OUT), 256>>>(bufA, Wl2, bl2, out, N, HL, OUT, 1);

    (void)n_in; (void)out_size;
}